// round 10
// baseline (speedup 1.0000x reference)
#include <cuda_runtime.h>
#include <cuda.h>
#include <math.h>
#include <stdint.h>

// ---------------- constants ----------------
#define NIMG 8
#define NUM_CLASSES 80
#define LCH 85
#define IMGF 640.0f
#define SCORE_T 0.1f
#define NMS_T 0.6f
#define DET 100
#define OBJ_CAP 32768
#define DCAP 4096
#define SORT_N 4096
#define TOPK 1000

// logit(0.1) = -2.197224577; margin 0.01 >> fp32 reduction-order wobble.
// Exact sigmoid recheck happens in cand_kernel, so superset is safe.
#define SCAN_T (-2.2072246f)

#define N_TILES 1400      // L0: 800 (P4=16), L1: 800..1200 (P4=8), L2: 1200..1400 (P4=4)
#define PIPE_GRID 592     // 4 CTAs/SM

__constant__ float2 c_anchors[3][3] = {
    {{6.1f, 8.1f}, {20.6f, 12.6f}, {11.2f, 23.7f}},
    {{36.2f, 26.8f}, {25.9f, 57.2f}, {57.8f, 47.9f}},
    {{122.1f, 78.3f}, {73.7f, 143.8f}, {236.1f, 213.1f}},
};

__device__ int g_cnt[9];       // [0]=obj cand count, [1+n]=det count (reset in nms)
__device__ int g_work;         // tile pop counter (reset in nms)
__device__ int g_objCand[OBJ_CAP];
__device__ float  g_detScore[NIMG][DCAP];
__device__ float4 g_detBox[NIMG][DCAP];
__device__ int    g_detInfo[NIMG][DCAP];

__device__ __forceinline__ float sigf(float x) { return 1.0f / (1.0f + expf(-x)); }

// ---------------- PTX helpers ----------------
__device__ __forceinline__ uint32_t smem_u32(const void* p) {
    uint32_t a;
    asm("{ .reg .u64 t; cvta.to.shared.u64 t, %1; cvt.u32.u64 %0, t; }" : "=r"(a) : "l"(p));
    return a;
}
#define MBARRIER_INIT(addr, count) \
    asm volatile("mbarrier.init.shared.b64 [%0], %1;" :: "r"(addr), "r"((uint32_t)(count)) : "memory")
#define MBARRIER_EXPECT_TX(addr, bytes) \
    asm volatile("mbarrier.arrive.expect_tx.shared.b64 _, [%0], %1;" :: "r"(addr), "r"((uint32_t)(bytes)) : "memory")
#define FENCE_PROXY_ASYNC() \
    asm volatile("fence.proxy.async.shared::cta;" ::: "memory")
#define MBARRIER_WAIT_PARITY(addr, parity) do {                                     \
    uint32_t _m = (addr), _p = (parity), _d;                                        \
    asm volatile("{\n\t.reg .pred p;\n\t"                                           \
        "mbarrier.try_wait.parity.acquire.cta.shared::cta.b64 p, [%1], %2;\n\t"     \
        "selp.b32 %0, 1, 0, p;\n\t}" : "=r"(_d) : "r"(_m), "r"(_p) : "memory");     \
    if (!_d) {                                                                      \
        asm volatile("{\n\t.reg .pred P1;\n\t"                                      \
        "WL_%=:\n\t"                                                                \
        "mbarrier.try_wait.parity.acquire.cta.shared::cta.b64 P1, [%0], %1, 0x989680;\n\t" \
        "@P1 bra.uni WD_%=;\n\t"                                                    \
        "bra.uni WL_%=;\n\t"                                                        \
        "WD_%=:\n\t}" :: "r"(_m), "r"(_p) : "memory");                              \
    }                                                                               \
} while (0)
#define TMA_LOAD_2D(dst, tmap, x, y, mbar) \
    asm volatile("cp.async.bulk.tensor.2d.shared::cta.global.tile.mbarrier::complete_tx::bytes " \
                 "[%0], [%1, {%2, %3}], [%4];"                                       \
                 :: "r"(dst), "l"(tmap), "r"(x), "r"(y), "r"(mbar) : "memory")

// ---------------- pass 1 (TMA pipeline): persistent CTAs, 4x8KB ring ----------------
// dyn smem layout:
//   [0      , 32768 )  ring: 4 x 8KB stages
//   [32768  , 43520 )  sw: obj weights, L0 3*128 | L1 3*256 | L2 3*512 floats
//   [43520  , 55808 )  red: 3 * 256 float4
//   [55808  , 55872 )  ctrl: s_cur, s_nxt, pad, mbar[4] @ +16
#define RING_OFF  0
#define SW_OFF    32768
#define RED_OFF   43520
#define CTRL_OFF  55808
#define DYN_SMEM  55872
#define STAGE_B   8192

struct TileInfo { int lvl, P4, CS, C, HW4, base4, swo; };

__device__ __forceinline__ TileInfo decode_tile(int t) {
    TileInfo ti;
    if (t < 800)       { ti.lvl = 0; ti.P4 = 16; ti.CS = 32;  ti.C = 128; ti.HW4 = 1600; ti.base4 = t * 16;          ti.swo = 0;    }
    else if (t < 1200) { ti.lvl = 1; ti.P4 = 8;  ti.CS = 64;  ti.C = 256; ti.HW4 = 400;  ti.base4 = (t - 800) * 8;   ti.swo = 384;  }
    else               { ti.lvl = 2; ti.P4 = 4;  ti.CS = 128; ti.C = 512; ti.HW4 = 100;  ti.base4 = (t - 1200) * 4;  ti.swo = 1152; }
    return ti;
}

__global__ __launch_bounds__(256) void obj_pipe_kernel(
    const __grid_constant__ CUtensorMap tm0,
    const __grid_constant__ CUtensorMap tm1,
    const __grid_constant__ CUtensorMap tm2,
    const float* __restrict__ w0, const float* __restrict__ w1, const float* __restrict__ w2,
    const float* __restrict__ b0, const float* __restrict__ b1, const float* __restrict__ b2)
{
    extern __shared__ char dyn[];
    float*  sw    = (float*)(dyn + SW_OFF);
    float4* red   = (float4*)(dyn + RED_OFF);
    int*    s_cur = (int*)(dyn + CTRL_OFF);
    int*    s_nxt = (int*)(dyn + CTRL_OFF + 4);
    uint32_t mb   = smem_u32(dyn + CTRL_OFF + 16);

    int tid = threadIdx.x;

    // stage all 3 levels' obj weights
    for (int i = tid; i < 3 * 128; i += 256) sw[i]        = __ldg(w0 + ((i / 128) * LCH + 4) * 128 + (i % 128));
    for (int i = tid; i < 3 * 256; i += 256) sw[384 + i]  = __ldg(w1 + ((i / 256) * LCH + 4) * 256 + (i % 256));
    for (int i = tid; i < 3 * 512; i += 256) sw[1152 + i] = __ldg(w2 + ((i / 512) * LCH + 4) * 512 + (i % 512));

    if (tid == 0) {
#pragma unroll
        for (int s = 0; s < 4; s++) MBARRIER_INIT(mb + s * 8, 1);
        FENCE_PROXY_ASYNC();
        int t0 = atomicAdd(&g_work, 1);
        *s_cur = t0;
        if (t0 < N_TILES) {
            TileInfo ti = decode_tile(t0);
            int n = ti.base4 / ti.HW4, q4 = ti.base4 - n * ti.HW4;
            int x = q4 * 4, y0 = n * ti.C;
            const CUtensorMap* tp = ti.lvl == 0 ? &tm0 : (ti.lvl == 1 ? &tm1 : &tm2);
#pragma unroll
            for (int s = 0; s < 4; s++) {
                MBARRIER_EXPECT_TX(mb + s * 8, STAGE_B);
                TMA_LOAD_2D(smem_u32(dyn + s * STAGE_B), tp, x, y0 + s * ti.CS, mb + s * 8);
            }
        }
        *s_nxt = atomicAdd(&g_work, 1);
    }
    __syncthreads();

    int localIdx = 0;
    int cur = *s_cur;

    while (cur < N_TILES) {
        TileInfo ti = decode_tile(cur);
        int P4 = ti.P4, CS = ti.CS, C = ti.C;
        int n = ti.base4 / ti.HW4, q4 = ti.base4 - n * ti.HW4;
        int pos = tid % P4, split = tid / P4;
        int cl = split * 2;
        const float* swL = sw + ti.swo;

        float4 A0 = make_float4(0.f, 0.f, 0.f, 0.f);
        float4 A1 = A0, A2 = A0;

        int nxt = *s_nxt;        // valid: written before last __syncthreads

#pragma unroll
        for (int s = 0; s < 4; s++) {
            MBARRIER_WAIT_PARITY(mb + s * 8, localIdx & 1);
            const float4* buf = (const float4*)(dyn + s * STAGE_B);
            float4 v0 = buf[cl * P4 + pos];
            float4 v1 = buf[(cl + 1) * P4 + pos];
            int ch = s * CS + cl;
            float wa0 = swL[ch],         wa1 = swL[ch + 1];
            float wb0 = swL[C + ch],     wb1 = swL[C + ch + 1];
            float wc0 = swL[2 * C + ch], wc1 = swL[2 * C + ch + 1];
            A0.x = fmaf(v0.x, wa0, A0.x); A0.y = fmaf(v0.y, wa0, A0.y);
            A0.z = fmaf(v0.z, wa0, A0.z); A0.w = fmaf(v0.w, wa0, A0.w);
            A0.x = fmaf(v1.x, wa1, A0.x); A0.y = fmaf(v1.y, wa1, A0.y);
            A0.z = fmaf(v1.z, wa1, A0.z); A0.w = fmaf(v1.w, wa1, A0.w);
            A1.x = fmaf(v0.x, wb0, A1.x); A1.y = fmaf(v0.y, wb0, A1.y);
            A1.z = fmaf(v0.z, wb0, A1.z); A1.w = fmaf(v0.w, wb0, A1.w);
            A1.x = fmaf(v1.x, wb1, A1.x); A1.y = fmaf(v1.y, wb1, A1.y);
            A1.z = fmaf(v1.z, wb1, A1.z); A1.w = fmaf(v1.w, wb1, A1.w);
            A2.x = fmaf(v0.x, wc0, A2.x); A2.y = fmaf(v0.y, wc0, A2.y);
            A2.z = fmaf(v0.z, wc0, A2.z); A2.w = fmaf(v0.w, wc0, A2.w);
            A2.x = fmaf(v1.x, wc1, A2.x); A2.y = fmaf(v1.y, wc1, A2.y);
            A2.z = fmaf(v1.z, wc1, A2.z); A2.w = fmaf(v1.w, wc1, A2.w);
            __syncthreads();                     // slot s fully consumed
            if (tid == 0 && nxt < N_TILES) {     // refill slot s with next tile's stage s
                TileInfo tn = decode_tile(nxt);
                int nn = tn.base4 / tn.HW4, nq4 = tn.base4 - nn * tn.HW4;
                const CUtensorMap* tp = tn.lvl == 0 ? &tm0 : (tn.lvl == 1 ? &tm1 : &tm2);
                MBARRIER_EXPECT_TX(mb + s * 8, STAGE_B);
                TMA_LOAD_2D(smem_u32(dyn + s * STAGE_B), tp, nq4 * 4, nn * tn.C + s * tn.CS, mb + s * 8);
            }
        }

        // per-tile reduction over splits (separate smem area; ring stays live)
        red[0 * 256 + tid] = A0;
        red[1 * 256 + tid] = A1;
        red[2 * 256 + tid] = A2;
        __syncthreads();
        for (int step = (256 / P4) / 2; step >= 1; step >>= 1) {
            if (tid < step * P4) {
#pragma unroll
                for (int a = 0; a < 3; a++) {
                    float4 xv = red[a * 256 + tid];
                    float4 yv = red[a * 256 + tid + step * P4];
                    xv.x += yv.x; xv.y += yv.y; xv.z += yv.z; xv.w += yv.w;
                    red[a * 256 + tid] = xv;
                }
            }
            __syncthreads();
        }
        if (tid < 3 * P4) {
            int a2 = tid / P4, p2 = tid % P4;
            const float* bp = ti.lvl == 0 ? b0 : (ti.lvl == 1 ? b1 : b2);
            float bias = __ldg(bp + a2 * LCH + 4);
            float4 acc = red[a2 * 256 + p2];
            float v[4] = {acc.x + bias, acc.y + bias, acc.z + bias, acc.w + bias};
            int q2 = q4 + p2;
#pragma unroll
            for (int k = 0; k < 4; k++) {
                if (v[k] > SCAN_T) {
                    int p = atomicAdd(&g_cnt[0], 1);
                    if (p < OBJ_CAP)
                        g_objCand[p] = (n << 17) | (ti.lvl << 15) | (a2 << 13) | (q2 * 4 + k);
                }
            }
        }

        if (tid == 0) {
            *s_cur = nxt;
            *s_nxt = atomicAdd(&g_work, 1);
        }
        localIdx++;
        __syncthreads();
        cur = *s_cur;
    }
}

// ---------------- pass 1 (LDG fallback): R7 uniform-tile version ----------------
#define OBJF_BLOCKS 700

template<int C, int HW, int LEVEL, int P>
__device__ __forceinline__ void obj_level_ldg(
    const float* __restrict__ f, const float* __restrict__ wgt, const float* __restrict__ b,
    int blkLocal, float* sw, float4* red, float* sb)
{
    constexpr int HW4  = HW / 4;
    constexpr int STOT = 256 / P;
    constexpr int CHN  = C / STOT;

    int tid  = threadIdx.x;
    int warp = tid >> 5, lane = tid & 31;

    for (int i = tid; i < 3 * C; i += 256) {
        int a = i / C, c = i - a * C;
        sw[i] = wgt[(a * LCH + 4) * C + c];
    }
    if (tid < 3) sb[tid] = b[tid * LCH + 4];
    __syncthreads();

    int pos   = lane % P;
    int sub   = lane / P;
    int split = warp * (32 / P) + sub;
    int c0    = split * CHN;

    int id = blkLocal * P + pos;
    int n = id / HW4, q = id - n * HW4;

    const float4* fb = (const float4*)f + ((size_t)n * C + c0) * HW4 + q;

    float4 A0 = make_float4(0.f, 0.f, 0.f, 0.f);
    float4 A1 = A0, A2 = A0;
#pragma unroll
    for (int cc = 0; cc < CHN; cc++) {
        float4 v = __ldg(fb + (size_t)cc * HW4);
        float w0v = sw[c0 + cc], w1v = sw[C + c0 + cc], w2v = sw[2 * C + c0 + cc];
        A0.x = fmaf(v.x, w0v, A0.x); A0.y = fmaf(v.y, w0v, A0.y);
        A0.z = fmaf(v.z, w0v, A0.z); A0.w = fmaf(v.w, w0v, A0.w);
        A1.x = fmaf(v.x, w1v, A1.x); A1.y = fmaf(v.y, w1v, A1.y);
        A1.z = fmaf(v.z, w1v, A1.z); A1.w = fmaf(v.w, w1v, A1.w);
        A2.x = fmaf(v.x, w2v, A2.x); A2.y = fmaf(v.y, w2v, A2.y);
        A2.z = fmaf(v.z, w2v, A2.z); A2.w = fmaf(v.w, w2v, A2.w);
    }
    red[0 * 256 + split * P + pos] = A0;
    red[1 * 256 + split * P + pos] = A1;
    red[2 * 256 + split * P + pos] = A2;
    __syncthreads();

    if (tid < 3 * P) {
        int a2 = tid / P, p2 = tid % P;
        float4 acc = red[a2 * 256 + p2];
#pragma unroll
        for (int s2 = 1; s2 < STOT; s2++) {
            float4 r = red[a2 * 256 + s2 * P + p2];
            acc.x += r.x; acc.y += r.y; acc.z += r.z; acc.w += r.w;
        }
        float bias = sb[a2];
        int id2 = blkLocal * P + p2;
        int n2 = id2 / HW4, q2 = id2 - n2 * HW4;
        float v[4] = {acc.x + bias, acc.y + bias, acc.z + bias, acc.w + bias};
#pragma unroll
        for (int k = 0; k < 4; k++) {
            if (v[k] > SCAN_T) {
                int p = atomicAdd(&g_cnt[0], 1);
                if (p < OBJ_CAP)
                    g_objCand[p] = (n2 << 17) | (LEVEL << 15) | (a2 << 13) | (q2 * 4 + k);
            }
        }
    }
}

__global__ __launch_bounds__(256, 5) void obj_ldg_kernel(
    const float* __restrict__ f0, const float* __restrict__ f1, const float* __restrict__ f2,
    const float* __restrict__ w0, const float* __restrict__ w1, const float* __restrict__ w2,
    const float* __restrict__ b0, const float* __restrict__ b1, const float* __restrict__ b2)
{
    __shared__ float sw[3 * 512];
    __shared__ float4 red[3 * 256];
    __shared__ float sb[3];

    int blk = blockIdx.x;
    if (blk < 400)      obj_level_ldg<128, 6400, 0, 32>(f0, w0, b0, blk,       sw, red, sb);
    else if (blk < 600) obj_level_ldg<256, 1600, 1, 16>(f1, w1, b1, blk - 400, sw, red, sb);
    else                obj_level_ldg<512, 400,  2, 8 >(f2, w2, b2, blk - 600, sw, red, sb);
}

// ------------- pass 2: full 85-channel head, 8 warps per block, exact recheck -------------
__global__ __launch_bounds__(256) void cand_kernel(
    const float* __restrict__ f0, const float* __restrict__ f1, const float* __restrict__ f2,
    const float* __restrict__ w0, const float* __restrict__ w1, const float* __restrict__ w2,
    const float* __restrict__ b0, const float* __restrict__ b1, const float* __restrict__ b2)
{
    __shared__ __align__(16) float shf[512];
    __shared__ float lg[LCH];
    __shared__ float4 s_box;
    __shared__ float s_obj;

    int total = g_cnt[0];
    if (total > OBJ_CAP) total = OBJ_CAP;

    int t = threadIdx.x;
    int warp = t >> 5, lane = t & 31;

    for (int ci = blockIdx.x; ci < total; ci += gridDim.x) {
        int pk = g_objCand[ci];
        int n = pk >> 17, level = (pk >> 15) & 3, a = (pk >> 13) & 3, hw = pk & 0x1FFF;

        const float *f, *w, *b;
        int C, HW, W, aoff;
        float stride;
        if (level == 0)      { f = f0; w = w0; b = b0; C = 128; HW = 6400; W = 80; stride = 8.f;  aoff = 0; }
        else if (level == 1) { f = f1; w = w1; b = b1; C = 256; HW = 1600; W = 40; stride = 16.f; aoff = 19200; }
        else                 { f = f2; w = w2; b = b2; C = 512; HW = 400;  W = 20; stride = 32.f; aoff = 24000; }

        for (int c = t; c < C; c += 256)
            shf[c] = f[((size_t)n * C + c) * HW + hw];
        __syncthreads();

        const float4* shf4 = (const float4*)shf;
        int C4 = C >> 2;
        for (int row = warp; row < LCH; row += 8) {
            const float4* wr = (const float4*)(w + (size_t)(a * LCH + row) * C);
            float acc = 0.f;
            for (int c4 = lane; c4 < C4; c4 += 32) {
                float4 wv = __ldg(wr + c4);
                float4 fv = shf4[c4];
                acc = fmaf(wv.x, fv.x, acc);
                acc = fmaf(wv.y, fv.y, acc);
                acc = fmaf(wv.z, fv.z, acc);
                acc = fmaf(wv.w, fv.w, acc);
            }
#pragma unroll
            for (int off = 16; off > 0; off >>= 1)
                acc += __shfl_xor_sync(0xFFFFFFFF, acc, off);
            if (lane == 0) lg[row] = acc + b[a * LCH + row];
        }
        __syncthreads();

        if (t == 0) {
            float px = sigf(lg[0]), py = sigf(lg[1]);
            float pw = sigf(lg[2]), ph = sigf(lg[3]);
            s_obj = sigf(lg[4]);
            int gx = hw % W, gy = hw / W;
            float2 anc = c_anchors[level][a];
            float cx = (2.f * px - 0.5f + (float)gx) * stride;
            float cy = (2.f * py - 0.5f + (float)gy) * stride;
            float bw = 4.f * pw * pw * anc.x;
            float bh = 4.f * ph * ph * anc.y;
            float x1 = cx - 0.5f * bw, y1 = cy - 0.5f * bh;
            float x2 = cx + 0.5f * bw, y2 = cy + 0.5f * bh;
            x1 = fminf(fmaxf(x1, 0.f), IMGF);
            y1 = fminf(fmaxf(y1, 0.f), IMGF);
            x2 = fminf(fmaxf(x2, 0.f), IMGF);
            y2 = fminf(fmaxf(y2, 0.f), IMGF);
            s_box = make_float4(x1, y1, x2, y2);
        }
        __syncthreads();

        if (t < NUM_CLASSES) {
            float ob = s_obj;
            if (ob > SCORE_T) {
                float s = ob * sigf(lg[5 + t]);
                if (s > SCORE_T) {
                    int pos = atomicAdd(&g_cnt[1 + n], 1);
                    if (pos < DCAP) {
                        g_detScore[n][pos] = s;
                        g_detBox[n][pos]   = s_box;
                        g_detInfo[n][pos]  = (aoff + hw * 3 + a) * NUM_CLASSES + t;
                    }
                }
            }
        }
        __syncthreads();
    }
}

// ------------- pass 3: adaptive sort + greedy NMS + output + counter reset -------------
__global__ void nms_kernel(const float* __restrict__ sf, float* __restrict__ out)
{
    extern __shared__ char smem[];
    unsigned long long* keys = (unsigned long long*)smem;
    int*    payload = (int*)   (smem + SORT_N * 8);
    float4* box     = (float4*)(smem + SORT_N * 12);
    float*  scr     = (float*) (smem + SORT_N * 12 + TOPK * 16);
    int*    lab     = (int*)   (smem + SORT_N * 12 + TOPK * 20);
    int*    val     = (int*)   (smem + SORT_N * 12 + TOPK * 24);
    __shared__ int picks[DET];
    __shared__ int s_sel, s_np;

    int n = blockIdx.x;
    int tid = threadIdx.x;
    int M = g_cnt[1 + n];
    if (M > DCAP) M = DCAP;
    if (tid == 0) s_np = 0;

    if (M > 0) {
        int sortN = 2;
        while (sortN < M) sortN <<= 1;

        for (int i = tid; i < sortN; i += blockDim.x) {
            if (i < M) {
                unsigned u = __float_as_uint(g_detScore[n][i]);
                u = (u & 0x80000000u) ? ~u : (u | 0x80000000u);
                keys[i] = ((unsigned long long)u << 32) | (unsigned)(0x7FFFFFFF - g_detInfo[n][i]);
                payload[i] = i;
            } else {
                keys[i] = 0ULL;
                payload[i] = -1;
            }
        }
        __syncthreads();

        for (int k = 2; k <= sortN; k <<= 1) {
            for (int j = k >> 1; j > 0; j >>= 1) {
                for (int i = tid; i < sortN; i += blockDim.x) {
                    int ixj = i ^ j;
                    if (ixj > i) {
                        bool up = ((i & k) == 0);
                        unsigned long long ka = keys[i], kb = keys[ixj];
                        bool sw = up ? (ka < kb) : (ka > kb);
                        if (sw) {
                            keys[i] = kb; keys[ixj] = ka;
                            int p = payload[i]; payload[i] = payload[ixj]; payload[ixj] = p;
                        }
                    }
                }
                __syncthreads();
            }
        }

        int M2 = M < TOPK ? M : TOPK;
        for (int i = tid; i < M2; i += blockDim.x) {
            int ci = payload[i];
            box[i] = g_detBox[n][ci];
            scr[i] = g_detScore[n][ci];
            lab[i] = g_detInfo[n][ci] % NUM_CLASSES;
            val[i] = 1;
        }
        __syncthreads();

        int cursor = 0;
        for (int iter = 0; iter < DET; iter++) {
            if (tid == 0) {
                int sel = -1;
                for (int j = cursor; j < M2; j++)
                    if (val[j]) { sel = j; break; }
                s_sel = sel;
                if (sel >= 0) {
                    picks[iter] = sel;
                    val[sel] = 0;
                    s_np = iter + 1;
                    cursor = sel + 1;
                }
            }
            __syncthreads();
            int sel = s_sel;
            if (sel < 0) break;
            float4 bs = box[sel];
            int ls = lab[sel];
            float areaS = (bs.z - bs.x) * (bs.w - bs.y);
            for (int j = tid; j < M2; j += blockDim.x) {
                if (val[j] && lab[j] == ls) {
                    float4 bj = box[j];
                    float ix1 = fmaxf(bs.x, bj.x), iy1 = fmaxf(bs.y, bj.y);
                    float ix2 = fminf(bs.z, bj.z), iy2 = fminf(bs.w, bj.w);
                    float iw = fmaxf(ix2 - ix1, 0.f), ih = fmaxf(iy2 - iy1, 0.f);
                    float inter = iw * ih;
                    float aj = (bj.z - bj.x) * (bj.w - bj.y);
                    float iou = inter / (areaS + aj - inter + 1e-7f);
                    if (iou > NMS_T) val[j] = 0;
                }
            }
            __syncthreads();
        }
        __syncthreads();
    }
    __syncthreads();

    int np = s_np;
    float s = sf[n];
    for (int d = tid; d < DET; d += blockDim.x) {
        float o0 = 0, o1 = 0, o2 = 0, o3 = 0, o4 = 0, o5 = 0;
        if (d < np) {
            int p = picks[d];
            float4 bbv = box[p];
            o0 = bbv.x / s; o1 = bbv.y / s; o2 = bbv.z / s; o3 = bbv.w / s;
            o4 = scr[p];
            o5 = (float)lab[p];
        }
        float* po = out + ((size_t)n * DET + d) * 6;
        po[0] = o0; po[1] = o1; po[2] = o2; po[3] = o3; po[4] = o4; po[5] = o5;
    }

    __syncthreads();
    if (tid == 0) {
        g_cnt[1 + n] = 0;
        if (n == 0) { g_cnt[0] = 0; g_work = 0; }
    }
}

// ---------------- host: tensormap encode via cudart driver entry point ----------------
typedef CUresult (*PFN_encodeTiled)(
    CUtensorMap*, CUtensorMapDataType, cuuint32_t, void*,
    const cuuint64_t*, const cuuint64_t*, const cuuint32_t*, const cuuint32_t*,
    CUtensorMapInterleave, CUtensorMapSwizzle, CUtensorMapL2promotion, CUtensorMapFloatOOBfill);

static PFN_encodeTiled get_encode_fn()
{
    void* p = nullptr;
    cudaDriverEntryPointQueryResult qr = cudaDriverEntryPointSymbolNotFound;
#if CUDART_VERSION >= 12050
    if (cudaGetDriverEntryPointByVersion("cuTensorMapEncodeTiled", &p, 12000,
                                         cudaEnableDefault, &qr) != cudaSuccess)
        p = nullptr;
#else
    if (cudaGetDriverEntryPoint("cuTensorMapEncodeTiled", &p,
                                cudaEnableDefault, &qr) != cudaSuccess)
        p = nullptr;
#endif
    if (qr != cudaDriverEntryPointSuccess) p = nullptr;
    return (PFN_encodeTiled)p;
}

static bool encode_map(PFN_encodeTiled fn, CUtensorMap* tm, const float* base,
                       uint64_t hw, uint64_t rows, uint32_t boxC, uint32_t boxR)
{
    cuuint64_t dims[2]    = {hw, rows};
    cuuint64_t strides[1] = {hw * 4};
    cuuint32_t box[2]     = {boxC, boxR};
    cuuint32_t elem[2]    = {1, 1};
    return fn(tm, CU_TENSOR_MAP_DATA_TYPE_FLOAT32, 2, (void*)base,
              dims, strides, box, elem,
              CU_TENSOR_MAP_INTERLEAVE_NONE, CU_TENSOR_MAP_SWIZZLE_NONE,
              CU_TENSOR_MAP_L2_PROMOTION_L2_128B,
              CU_TENSOR_MAP_FLOAT_OOB_FILL_NONE) == CUDA_SUCCESS;
}

// ---------------- launch ----------------
extern "C" void kernel_launch(void* const* d_in, const int* in_sizes, int n_in,
                              void* d_out, int out_size)
{
    const float *f0 = nullptr, *f1 = nullptr, *f2 = nullptr;
    const float *w0 = nullptr, *w1 = nullptr, *w2 = nullptr;
    const float *bbp[3] = {nullptr, nullptr, nullptr};
    const float *sf = nullptr;
    int bcount = 0;
    for (int i = 0; i < n_in; i++) {
        const float* p = (const float*)d_in[i];
        switch (in_sizes[i]) {
            case 6553600: f0 = p; break;
            case 3276800: f1 = p; break;
            case 1638400: f2 = p; break;
            case 32640:   w0 = p; break;
            case 65280:   w1 = p; break;
            case 130560:  w2 = p; break;
            case 255:     if (bcount < 3) bbp[bcount++] = p; break;
            case 8:       sf = p; break;
            default: break;
        }
    }
    const float *b0 = bbp[0], *b1 = bbp[1], *b2 = bbp[2];
    float* out = (float*)d_out;

    PFN_encodeTiled enc = get_encode_fn();
    bool tma_ok = false;
    CUtensorMap tm0, tm1, tm2;
    if (enc) {
        // 8KB stage boxes: L0 {64el,32ch} L1 {32el,64ch} L2 {16el,128ch}
        tma_ok = encode_map(enc, &tm0, f0, 6400, (uint64_t)NIMG * 128, 64, 32)
              && encode_map(enc, &tm1, f1, 1600, (uint64_t)NIMG * 256, 32, 64)
              && encode_map(enc, &tm2, f2, 400,  (uint64_t)NIMG * 512, 16, 128);
    }

    if (tma_ok) {
        cudaFuncSetAttribute(obj_pipe_kernel, cudaFuncAttributeMaxDynamicSharedMemorySize, DYN_SMEM);
        obj_pipe_kernel<<<PIPE_GRID, 256, DYN_SMEM>>>(tm0, tm1, tm2, w0, w1, w2, b0, b1, b2);
    } else {
        obj_ldg_kernel<<<OBJF_BLOCKS, 256>>>(f0, f1, f2, w0, w1, w2, b0, b1, b2);
    }

    cand_kernel<<<320, 256>>>(f0, f1, f2, w0, w1, w2, b0, b1, b2);

    size_t nms_smem = SORT_N * 12 + TOPK * 28;
    cudaFuncSetAttribute(nms_kernel, cudaFuncAttributeMaxDynamicSharedMemorySize, (int)nms_smem);
    nms_kernel<<<NIMG, 256, nms_smem>>>(sf, out);
}

// round 11
// speedup vs baseline: 1.1380x; 1.1380x over previous
#include <cuda_runtime.h>
#include <math.h>
#include <stdint.h>

// ---------------- constants ----------------
#define NIMG 8
#define NUM_CLASSES 80
#define LCH 85
#define IMGF 640.0f
#define SCORE_T 0.1f
#define NMS_T 0.6f
#define DET 100
#define OBJ_CAP 32768
#define DCAP 1024
#define TOPK 1000

// logit(0.1) = -2.197224577; margin 0.01 >> fp32 reduction-order wobble.
// Exact sigmoid recheck happens in the cand phase, so superset is safe.
#define SCAN_T (-2.2072246f)

#define N_TILES 1400       // 800 L0 + 400 L1 + 200 L2, 32KB each
#define GRID 592           // 4 CTAs/SM on 148 SMs — all resident (required for barriers)

// dyn smem (40960 B):
//  phase1: sw 10752 | sb 36 | red @10816 (12288)
//  phase2: shf 2048 | lg 340
//  phase3: keys@0 8192 | payload@8192 4096 | box@12288 16384 | scr@28672 4096 | lab@32768 4096 | val@36864 4096
#define DYN_SMEM 40960

__constant__ float2 c_anchors[3][3] = {
    {{6.1f, 8.1f}, {20.6f, 12.6f}, {11.2f, 23.7f}},
    {{36.2f, 26.8f}, {25.9f, 57.2f}, {57.8f, 47.9f}},
    {{122.1f, 78.3f}, {73.7f, 143.8f}, {236.1f, 213.1f}},
};

// statically zero-initialized; reset at end of each kernel run
__device__ int g_cnt[9];       // [0]=obj cand count, [1+n]=det count
__device__ int g_work;         // obj tile pop counter
__device__ int g_bar1, g_bar2, g_bar3;
__device__ int g_objCand[OBJ_CAP];
__device__ float  g_detScore[NIMG][DCAP];
__device__ float4 g_detBox[NIMG][DCAP];
__device__ int    g_detInfo[NIMG][DCAP];

__device__ __forceinline__ float sigf(float x) { return 1.0f / (1.0f + expf(-x)); }

__device__ __forceinline__ int ld_acq(const int* p) {
    int v;
    asm volatile("ld.acquire.gpu.global.s32 %0, [%1];" : "=r"(v) : "l"(p) : "memory");
    return v;
}
__device__ __forceinline__ void bar_arrive(int* c) {
    __syncthreads();
    if (threadIdx.x == 0) { __threadfence(); atomicAdd(c, 1); }
}
__device__ __forceinline__ void bar_wait(int* c, int tgt) {
    if (threadIdx.x == 0) {
        while (ld_acq(c) < tgt) __nanosleep(128);
        __threadfence();
    }
    __syncthreads();
}

// ================= mega kernel: obj -> barrier -> cand -> barrier -> nms =================
__global__ __launch_bounds__(256, 4) void mega_kernel(
    const float* __restrict__ f0, const float* __restrict__ f1, const float* __restrict__ f2,
    const float* __restrict__ w0, const float* __restrict__ w1, const float* __restrict__ w2,
    const float* __restrict__ b0, const float* __restrict__ b1, const float* __restrict__ b2,
    const float* __restrict__ sf, float* __restrict__ out)
{
    extern __shared__ char dyn[];
    int tid = threadIdx.x;

    // ---------------- PHASE 1: objectness screen ----------------
    {
        float*  sw  = (float*)dyn;                  // 2688 floats
        float*  sb  = (float*)(dyn + 10752);        // 9 floats
        float4* red = (float4*)(dyn + 10816);       // 3*256 float4
        __shared__ int s_tile;

        for (int i = tid; i < 384; i += 256)
            sw[i] = __ldg(w0 + ((i >> 7) * LCH + 4) * 128 + (i & 127));
        for (int i = tid; i < 768; i += 256)
            sw[384 + i] = __ldg(w1 + ((i >> 8) * LCH + 4) * 256 + (i & 255));
        for (int i = tid; i < 1536; i += 256)
            sw[1152 + i] = __ldg(w2 + ((i >> 9) * LCH + 4) * 512 + (i & 511));
        if (tid < 9) {
            int lvl = tid / 3, a = tid - lvl * 3;
            const float* bp = lvl == 0 ? b0 : (lvl == 1 ? b1 : b2);
            sb[tid] = __ldg(bp + a * LCH + 4);
        }
        __syncthreads();

        while (true) {
            if (tid == 0) s_tile = atomicAdd(&g_work, 1);
            __syncthreads();
            int t = s_tile;
            if (t >= N_TILES) break;

            int lvl, p4s, C, HW4, base4, swo;
            const float* f;
            if (t < 800)       { lvl = 0; p4s = 4; C = 128; HW4 = 1600; base4 = t << 4;          swo = 0;    f = f0; }
            else if (t < 1200) { lvl = 1; p4s = 3; C = 256; HW4 = 400;  base4 = (t - 800) << 3;  swo = 384;  f = f1; }
            else               { lvl = 2; p4s = 2; C = 512; HW4 = 100;  base4 = (t - 1200) << 2; swo = 1152; f = f2; }
            int P4 = 1 << p4s;
            int n = base4 / HW4, q4 = base4 - n * HW4;
            int pos = tid & (P4 - 1), split = tid >> p4s;
            int c0 = split * 8;
            const float4* fb = (const float4*)f + ((size_t)n * C + c0) * HW4 + q4 + pos;
            const float* swL = sw + swo;

            float4 A0 = make_float4(0.f, 0.f, 0.f, 0.f);
            float4 A1 = A0, A2 = A0;
#pragma unroll
            for (int cc = 0; cc < 8; cc++) {
                float4 v = __ldg(fb + (size_t)cc * HW4);
                float wa = swL[c0 + cc], wb = swL[C + c0 + cc], wc = swL[2 * C + c0 + cc];
                A0.x = fmaf(v.x, wa, A0.x); A0.y = fmaf(v.y, wa, A0.y);
                A0.z = fmaf(v.z, wa, A0.z); A0.w = fmaf(v.w, wa, A0.w);
                A1.x = fmaf(v.x, wb, A1.x); A1.y = fmaf(v.y, wb, A1.y);
                A1.z = fmaf(v.z, wb, A1.z); A1.w = fmaf(v.w, wb, A1.w);
                A2.x = fmaf(v.x, wc, A2.x); A2.y = fmaf(v.y, wc, A2.y);
                A2.z = fmaf(v.z, wc, A2.z); A2.w = fmaf(v.w, wc, A2.w);
            }
            red[0 * 256 + tid] = A0;
            red[1 * 256 + tid] = A1;
            red[2 * 256 + tid] = A2;
            __syncthreads();

            int SPLITS = 256 >> p4s;
            for (int step = SPLITS >> 1; step >= 1; step >>= 1) {
                if (tid < step * P4) {
#pragma unroll
                    for (int a = 0; a < 3; a++) {
                        float4 xv = red[a * 256 + tid];
                        float4 yv = red[a * 256 + tid + step * P4];
                        xv.x += yv.x; xv.y += yv.y; xv.z += yv.z; xv.w += yv.w;
                        red[a * 256 + tid] = xv;
                    }
                }
                __syncthreads();
            }
            if (tid < 3 * P4) {
                int a2 = tid >> p4s, p2 = tid & (P4 - 1);
                float bias = sb[lvl * 3 + a2];
                float4 acc = red[a2 * 256 + p2];
                float v[4] = {acc.x + bias, acc.y + bias, acc.z + bias, acc.w + bias};
                int q2 = q4 + p2;
#pragma unroll
                for (int k = 0; k < 4; k++) {
                    if (v[k] > SCAN_T) {
                        int p = atomicAdd(&g_cnt[0], 1);
                        if (p < OBJ_CAP)
                            g_objCand[p] = (n << 17) | (lvl << 15) | (a2 << 13) | (q2 * 4 + k);
                    }
                }
            }
            __syncthreads();
        }
    }

    bar_arrive(&g_bar1);
    bar_wait(&g_bar1, GRID);

    // ---------------- PHASE 2: full 85-channel head for candidates ----------------
    {
        float* shf = (float*)dyn;                  // 512 floats
        float* lg  = (float*)(dyn + 2048);         // 85 floats
        __shared__ float4 s_box;
        __shared__ float s_obj;
        __shared__ int s_total;

        if (tid == 0) s_total = atomicAdd(&g_cnt[0], 0);
        __syncthreads();
        int total = s_total;
        if (total > OBJ_CAP) total = OBJ_CAP;

        int warp = tid >> 5, lane = tid & 31;

        for (int ci = blockIdx.x; ci < total; ci += GRID) {
            int pk = g_objCand[ci];
            int n = pk >> 17, level = (pk >> 15) & 3, a = (pk >> 13) & 3, hw = pk & 0x1FFF;

            const float *f, *w, *b;
            int C, HW, W, aoff;
            float stride;
            if (level == 0)      { f = f0; w = w0; b = b0; C = 128; HW = 6400; W = 80; stride = 8.f;  aoff = 0; }
            else if (level == 1) { f = f1; w = w1; b = b1; C = 256; HW = 1600; W = 40; stride = 16.f; aoff = 19200; }
            else                 { f = f2; w = w2; b = b2; C = 512; HW = 400;  W = 20; stride = 32.f; aoff = 24000; }

            for (int c = tid; c < C; c += 256)
                shf[c] = f[((size_t)n * C + c) * HW + hw];
            __syncthreads();

            const float4* shf4 = (const float4*)shf;
            int C4 = C >> 2;
            for (int row = warp; row < LCH; row += 8) {
                const float4* wr = (const float4*)(w + (size_t)(a * LCH + row) * C);
                float acc = 0.f;
                for (int c4 = lane; c4 < C4; c4 += 32) {
                    float4 wv = __ldg(wr + c4);
                    float4 fv = shf4[c4];
                    acc = fmaf(wv.x, fv.x, acc);
                    acc = fmaf(wv.y, fv.y, acc);
                    acc = fmaf(wv.z, fv.z, acc);
                    acc = fmaf(wv.w, fv.w, acc);
                }
#pragma unroll
                for (int off = 16; off > 0; off >>= 1)
                    acc += __shfl_xor_sync(0xFFFFFFFF, acc, off);
                if (lane == 0) lg[row] = acc + __ldg(b + a * LCH + row);
            }
            __syncthreads();

            if (tid == 0) {
                float px = sigf(lg[0]), py = sigf(lg[1]);
                float pw = sigf(lg[2]), ph = sigf(lg[3]);
                s_obj = sigf(lg[4]);
                int gx = hw % W, gy = hw / W;
                float2 anc = c_anchors[level][a];
                float cx = (2.f * px - 0.5f + (float)gx) * stride;
                float cy = (2.f * py - 0.5f + (float)gy) * stride;
                float bw = 4.f * pw * pw * anc.x;
                float bh = 4.f * ph * ph * anc.y;
                float x1 = cx - 0.5f * bw, y1 = cy - 0.5f * bh;
                float x2 = cx + 0.5f * bw, y2 = cy + 0.5f * bh;
                x1 = fminf(fmaxf(x1, 0.f), IMGF);
                y1 = fminf(fmaxf(y1, 0.f), IMGF);
                x2 = fminf(fmaxf(x2, 0.f), IMGF);
                y2 = fminf(fmaxf(y2, 0.f), IMGF);
                s_box = make_float4(x1, y1, x2, y2);
            }
            __syncthreads();

            if (tid < NUM_CLASSES) {
                float ob = s_obj;
                if (ob > SCORE_T) {
                    float s = ob * sigf(lg[5 + tid]);
                    if (s > SCORE_T) {
                        int pos = atomicAdd(&g_cnt[1 + n], 1);
                        if (pos < DCAP) {
                            g_detScore[n][pos] = s;
                            g_detBox[n][pos]   = s_box;
                            g_detInfo[n][pos]  = (aoff + hw * 3 + a) * NUM_CLASSES + tid;
                        }
                    }
                }
            }
            __syncthreads();
        }
    }

    bar_arrive(&g_bar2);
    if (blockIdx.x >= NIMG) return;         // only 8 blocks continue
    bar_wait(&g_bar2, GRID);

    // ---------------- PHASE 3: sort + greedy NMS + output ----------------
    {
        unsigned long long* keys = (unsigned long long*)dyn;       // 1024 * 8
        int*    payload = (int*)   (dyn + 8192);                   // 1024 * 4
        float4* box     = (float4*)(dyn + 12288);                  // 1024 * 16
        float*  scr     = (float*) (dyn + 28672);                  // 1024 * 4
        int*    lab     = (int*)   (dyn + 32768);                  // 1024 * 4
        int*    val     = (int*)   (dyn + 36864);                  // 1024 * 4
        __shared__ int picks[DET];
        __shared__ int s_sel, s_np, s_M;

        int n = blockIdx.x;
        if (tid == 0) { s_np = 0; s_M = atomicAdd(&g_cnt[1 + n], 0); }
        __syncthreads();
        int M = s_M;
        if (M > DCAP) M = DCAP;

        if (M > 0) {
            int sortN = 2;
            while (sortN < M) sortN <<= 1;

            for (int i = tid; i < sortN; i += 256) {
                if (i < M) {
                    unsigned u = __float_as_uint(g_detScore[n][i]);
                    u = (u & 0x80000000u) ? ~u : (u | 0x80000000u);
                    keys[i] = ((unsigned long long)u << 32) | (unsigned)(0x7FFFFFFF - g_detInfo[n][i]);
                    payload[i] = i;
                } else {
                    keys[i] = 0ULL;
                    payload[i] = -1;
                }
            }
            __syncthreads();

            for (int k = 2; k <= sortN; k <<= 1) {
                for (int j = k >> 1; j > 0; j >>= 1) {
                    for (int i = tid; i < sortN; i += 256) {
                        int ixj = i ^ j;
                        if (ixj > i) {
                            bool up = ((i & k) == 0);
                            unsigned long long ka = keys[i], kb = keys[ixj];
                            bool sw = up ? (ka < kb) : (ka > kb);
                            if (sw) {
                                keys[i] = kb; keys[ixj] = ka;
                                int p = payload[i]; payload[i] = payload[ixj]; payload[ixj] = p;
                            }
                        }
                    }
                    __syncthreads();
                }
            }

            int M2 = M < TOPK ? M : TOPK;
            for (int i = tid; i < M2; i += 256) {
                int ci = payload[i];
                box[i] = g_detBox[n][ci];
                scr[i] = g_detScore[n][ci];
                lab[i] = g_detInfo[n][ci] % NUM_CLASSES;
                val[i] = 1;
            }
            __syncthreads();

            int cursor = 0;
            for (int iter = 0; iter < DET; iter++) {
                if (tid == 0) {
                    int sel = -1;
                    for (int j = cursor; j < M2; j++)
                        if (val[j]) { sel = j; break; }
                    s_sel = sel;
                    if (sel >= 0) {
                        picks[iter] = sel;
                        val[sel] = 0;
                        s_np = iter + 1;
                        cursor = sel + 1;
                    }
                }
                __syncthreads();
                int sel = s_sel;
                if (sel < 0) break;
                float4 bs = box[sel];
                int ls = lab[sel];
                float areaS = (bs.z - bs.x) * (bs.w - bs.y);
                for (int j = tid; j < M2; j += 256) {
                    if (val[j] && lab[j] == ls) {
                        float4 bj = box[j];
                        float ix1 = fmaxf(bs.x, bj.x), iy1 = fmaxf(bs.y, bj.y);
                        float ix2 = fminf(bs.z, bj.z), iy2 = fminf(bs.w, bj.w);
                        float iw = fmaxf(ix2 - ix1, 0.f), ih = fmaxf(iy2 - iy1, 0.f);
                        float inter = iw * ih;
                        float aj = (bj.z - bj.x) * (bj.w - bj.y);
                        float iou = inter / (areaS + aj - inter + 1e-7f);
                        if (iou > NMS_T) val[j] = 0;
                    }
                }
                __syncthreads();
            }
            __syncthreads();
        }
        __syncthreads();

        int np = s_np;
        float s = __ldg(sf + n);
        for (int d = tid; d < DET; d += 256) {
            float o0 = 0, o1 = 0, o2 = 0, o3 = 0, o4 = 0, o5 = 0;
            if (d < np) {
                int p = picks[d];
                float4 bbv = box[p];
                o0 = bbv.x / s; o1 = bbv.y / s; o2 = bbv.z / s; o3 = bbv.w / s;
                o4 = scr[p];
                o5 = (float)lab[p];
            }
            float* po = out + ((size_t)n * DET + d) * 6;
            po[0] = o0; po[1] = o1; po[2] = o2; po[3] = o3; po[4] = o4; po[5] = o5;
        }

        // -------- reset counters for next graph replay --------
        __syncthreads();
        if (tid == 0) {
            g_cnt[1 + n] = 0;
            __threadfence();
            atomicAdd(&g_bar3, 1);
            if (n == 0) {
                while (ld_acq(&g_bar3) < NIMG) __nanosleep(128);
                g_cnt[0] = 0;
                g_work = 0;
                g_bar1 = 0;
                g_bar2 = 0;
                g_bar3 = 0;
            }
        }
    }
}

// ---------------- launch ----------------
extern "C" void kernel_launch(void* const* d_in, const int* in_sizes, int n_in,
                              void* d_out, int out_size)
{
    const float *f0 = nullptr, *f1 = nullptr, *f2 = nullptr;
    const float *w0 = nullptr, *w1 = nullptr, *w2 = nullptr;
    const float *bbp[3] = {nullptr, nullptr, nullptr};
    const float *sf = nullptr;
    int bcount = 0;
    for (int i = 0; i < n_in; i++) {
        const float* p = (const float*)d_in[i];
        switch (in_sizes[i]) {
            case 6553600: f0 = p; break;
            case 3276800: f1 = p; break;
            case 1638400: f2 = p; break;
            case 32640:   w0 = p; break;
            case 65280:   w1 = p; break;
            case 130560:  w2 = p; break;
            case 255:     if (bcount < 3) bbp[bcount++] = p; break;
            case 8:       sf = p; break;
            default: break;
        }
    }
    const float *b0 = bbp[0], *b1 = bbp[1], *b2 = bbp[2];
    float* out = (float*)d_out;

    cudaFuncSetAttribute(mega_kernel, cudaFuncAttributeMaxDynamicSharedMemorySize, DYN_SMEM);
    mega_kernel<<<GRID, 256, DYN_SMEM>>>(f0, f1, f2, w0, w1, w2, b0, b1, b2, sf, out);
}